// round 3
// baseline (speedup 1.0000x reference)
#include <cuda_runtime.h>
#include <cstddef>

// LSTM_824633721296: 2-layer LSTM (B=1024, T=512, I=8, H=64) + FC (O=10)
// 128 blocks x 512 threads, 8 batch/block. Weights in SMEM.
// Warp layout: lane = (batch 4) x (rowgroup 8); thread covers 4 rows (j-stride 64),
// 1 batch. Weight LDS.128 -> 8 distinct granules + 4-way broadcast = 1 wavefront.

#define BT        8
#define NB        128
#define NTHREADS  512
#define HID       64
#define NG        256
#define TSTEPS    512
#define IDIM      8
#define ODIM      10

#define W0_STRIDE 76      // 19 f4 (odd) -> conflict-free 8-row granule spread
#define W1_STRIDE 132     // 33 f4 (odd)
#define HSTR      68      // 17 f4 (odd) -> batch-granules distinct
#define XSTR      12      // 3 f4 (odd)
#define GSTR      264     // b*264 mod 32 = 8b -> store pattern hits all 32 banks

// smem layout (floats)
#define OFF_W0    0
#define OFF_W1    (OFF_W0 + 256*W0_STRIDE)        // 19456
#define OFF_G     (OFF_W1 + 256*W1_STRIDE)        // 53248
#define OFF_H0    (OFF_G  + BT*GSTR)              // 55360
#define OFF_H1    (OFF_H0 + 2*BT*HSTR)            // 56448
#define OFF_XS    (OFF_H1 + 2*BT*HSTR)            // 57536
#define SMEM_FLOATS (OFF_XS + 2*BT*XSTR)          // 57728 floats = 230912 B

__device__ __forceinline__ float sigm_(float x) {
    return __fdividef(1.0f, 1.0f + __expf(-x));
}
__device__ __forceinline__ float tanh_(float x) {
    return 1.0f - __fdividef(2.0f, __expf(2.0f * x) + 1.0f);
}

__device__ __forceinline__ void ffma2(unsigned long long& acc,
                                      unsigned long long a,
                                      unsigned long long w) {
    asm("fma.rn.f32x2 %0, %1, %2, %0;" : "+l"(acc) : "l"(a), "l"(w));
}
__device__ __forceinline__ float hsum2(unsigned long long v) {
    float lo, hi;
    asm("mov.b64 {%0, %1}, %2;" : "=f"(lo), "=f"(hi) : "l"(v));
    return lo + hi;
}
__device__ __forceinline__ unsigned long long packbias(float b) {
    return (unsigned long long)__float_as_uint(b);
}

extern __shared__ float smem[];

__global__ void __launch_bounds__(NTHREADS, 1)
lstm_persistent_kernel(const float* __restrict__ x,
                       const float* __restrict__ w_ih0, const float* __restrict__ w_hh0,
                       const float* __restrict__ b_ih0, const float* __restrict__ b_hh0,
                       const float* __restrict__ w_ih1, const float* __restrict__ w_hh1,
                       const float* __restrict__ b_ih1, const float* __restrict__ b_hh1,
                       const float* __restrict__ w_fc,  const float* __restrict__ b_fc,
                       float* __restrict__ out)
{
    float* W0    = smem + OFF_W0;   // [256][76]  cols 0..7 = w_ih0, 8..71 = w_hh0
    float* W1    = smem + OFF_W1;   // [256][132] cols 0..63 = w_ih1, 64..127 = w_hh1
    float* gates = smem + OFF_G;    // [8][264]
    float* h0s   = smem + OFF_H0;   // [2][8][68]
    float* h1s   = smem + OFF_H1;   // [2][8][68]
    float* xs    = smem + OFF_XS;   // [2][8][12]

    const int tid = threadIdx.x;
    const int b0  = blockIdx.x * BT;

    // ---- stage weights into SMEM ----
    for (int i = tid; i < 256 * 8;  i += NTHREADS) W0[(i >> 3) * W0_STRIDE + (i & 7)]       = w_ih0[i];
    for (int i = tid; i < 256 * 64; i += NTHREADS) W0[(i >> 6) * W0_STRIDE + 8 + (i & 63)]  = w_hh0[i];
    for (int i = tid; i < 256 * 64; i += NTHREADS) W1[(i >> 6) * W1_STRIDE + (i & 63)]      = w_ih1[i];
    for (int i = tid; i < 256 * 64; i += NTHREADS) W1[(i >> 6) * W1_STRIDE + 64 + (i & 63)] = w_hh1[i];
    for (int i = tid; i < 2 * BT * HSTR; i += NTHREADS) { h0s[i] = 0.0f; h1s[i] = 0.0f; }

    // x(t=0) -> xs buffer 0
    if (tid < 16) {
        int b = tid >> 1, q = tid & 1;
        float4 v = *(const float4*)(x + (size_t)(b0 + b) * TSTEPS * IDIM + q * 4);
        *(float4*)(xs + b * XSTR + q * 4) = v;
    }

    // ---- GEMM mapping: warp = 4 batches x 8 rowgroups; thread = 1 batch x 4 rows ----
    const int w    = tid >> 5;
    const int lane = tid & 31;
    const int bg   = (w >> 3) * 4 + (lane & 3);      // this thread's batch (0..7)
    const int rb   = ((w & 7) << 3) + (lane >> 2);   // row base (0..63); rows rb+64j

    float bias0[4], bias1[4];
    #pragma unroll
    for (int j = 0; j < 4; j++) {
        int r = rb + 64 * j;
        bias0[j] = b_ih0[r] + b_hh0[r];
        bias1[j] = b_ih1[r] + b_hh1[r];
    }

    // ---- elementwise mapping: one (eb, eh) per thread per layer ----
    const int eb = tid >> 6;      // 0..7
    const int eh = tid & 63;
    float c0 = 0.0f, c1 = 0.0f;

    __syncthreads();

    const float4* w0p[4];
    const float4* w1p[4];
    #pragma unroll
    for (int j = 0; j < 4; j++) {
        int r = rb + 64 * j;
        w0p[j] = (const float4*)(W0 + r * W0_STRIDE);
        w1p[j] = (const float4*)(W1 + r * W1_STRIDE);
    }

    for (int t = 0; t < TSTEPS; t++) {
        const int p  = t & 1;
        const int pn = p ^ 1;

        // prefetch x(t+1)
        float4 xpre = make_float4(0.f, 0.f, 0.f, 0.f);
        const bool doPre = (tid < 16) && (t + 1 < TSTEPS);
        if (doPre) {
            int b = tid >> 1, q = tid & 1;
            xpre = *(const float4*)(x + (size_t)(b0 + b) * TSTEPS * IDIM + (size_t)(t + 1) * IDIM + q * 4);
        }

        unsigned long long acc[4];

        // ========== GEMM 0: gates = [x_t | h0] @ W0^T + bias ==========
        #pragma unroll
        for (int j = 0; j < 4; j++) acc[j] = packbias(bias0[j]);
        {
            const ulonglong2* xq = (const ulonglong2*)(xs + p * (BT * XSTR) + bg * XSTR);
            const ulonglong2* hq = (const ulonglong2*)(h0s + p * (BT * HSTR) + bg * HSTR);
            #pragma unroll
            for (int q = 0; q < 2; q++) {            // x part (K=8)
                ulonglong2 av = xq[q];
                #pragma unroll
                for (int j = 0; j < 4; j++) {
                    ulonglong2 wv = *(const ulonglong2*)(w0p[j] + q);
                    ffma2(acc[j], av.x, wv.x);
                    ffma2(acc[j], av.y, wv.y);
                }
            }
            #pragma unroll
            for (int q = 0; q < 16; q++) {           // h part (K=64)
                ulonglong2 av = hq[q];
                #pragma unroll
                for (int j = 0; j < 4; j++) {
                    ulonglong2 wv = *(const ulonglong2*)(w0p[j] + 2 + q);
                    ffma2(acc[j], av.x, wv.x);
                    ffma2(acc[j], av.y, wv.y);
                }
            }
        }
        #pragma unroll
        for (int j = 0; j < 4; j++)
            gates[bg * GSTR + rb + 64 * j] = hsum2(acc[j]);
        __syncthreads();

        // ========== ELEM 0 ==========
        {
            const float* g = gates + eb * GSTR;
            float iv = sigm_(g[eh]);
            float fv = sigm_(g[64 + eh]);
            float gv = tanh_(g[128 + eh]);
            float ov = sigm_(g[192 + eh]);
            c0 = fv * c0 + iv * gv;
            h0s[pn * (BT * HSTR) + eb * HSTR + eh] = ov * tanh_(c0);
        }
        __syncthreads();

        // ========== GEMM 1: gates = [h0_new | h1] @ W1^T + bias ==========
        #pragma unroll
        for (int j = 0; j < 4; j++) acc[j] = packbias(bias1[j]);
        {
            const ulonglong2* h0q = (const ulonglong2*)(h0s + pn * (BT * HSTR) + bg * HSTR);
            const ulonglong2* h1q = (const ulonglong2*)(h1s + p  * (BT * HSTR) + bg * HSTR);
            #pragma unroll
            for (int q = 0; q < 16; q++) {           // h0_new part
                ulonglong2 av = h0q[q];
                #pragma unroll
                for (int j = 0; j < 4; j++) {
                    ulonglong2 wv = *(const ulonglong2*)(w1p[j] + q);
                    ffma2(acc[j], av.x, wv.x);
                    ffma2(acc[j], av.y, wv.y);
                }
            }
            #pragma unroll
            for (int q = 0; q < 16; q++) {           // h1 part
                ulonglong2 av = h1q[q];
                #pragma unroll
                for (int j = 0; j < 4; j++) {
                    ulonglong2 wv = *(const ulonglong2*)(w1p[j] + 16 + q);
                    ffma2(acc[j], av.x, wv.x);
                    ffma2(acc[j], av.y, wv.y);
                }
            }
        }
        #pragma unroll
        for (int j = 0; j < 4; j++)
            gates[bg * GSTR + rb + 64 * j] = hsum2(acc[j]);
        if (doPre) {
            int b = tid >> 1, q = tid & 1;
            *(float4*)(xs + pn * (BT * XSTR) + b * XSTR + q * 4) = xpre;
        }
        __syncthreads();

        // ========== ELEM 1 ==========
        {
            const float* g = gates + eb * GSTR;
            float iv = sigm_(g[eh]);
            float fv = sigm_(g[64 + eh]);
            float gv = tanh_(g[128 + eh]);
            float ov = sigm_(g[192 + eh]);
            c1 = fv * c1 + iv * gv;
            h1s[pn * (BT * HSTR) + eb * HSTR + eh] = ov * tanh_(c1);
        }
        __syncthreads();
    }

    // ========== FC: out = h1_final @ w_fc^T + b_fc ==========
    // after t=511: p=1 -> final h1 in buffer 0
    if (tid < BT * ODIM) {
        int b = tid / ODIM, o = tid % ODIM;
        const float* hrow = h1s + b * HSTR;
        const float* wrow = w_fc + o * HID;
        float s = b_fc[o];
        #pragma unroll 16
        for (int k = 0; k < HID; k++) s = fmaf(hrow[k], wrow[k], s);
        out[(size_t)(b0 + b) * ODIM + o] = s;
    }
}

extern "C" void kernel_launch(void* const* d_in, const int* in_sizes, int n_in,
                              void* d_out, int out_size)
{
    (void)in_sizes; (void)n_in; (void)out_size;
    const float* x     = (const float*)d_in[0];
    const float* w_ih0 = (const float*)d_in[1];
    const float* w_hh0 = (const float*)d_in[2];
    const float* b_ih0 = (const float*)d_in[3];
    const float* b_hh0 = (const float*)d_in[4];
    const float* w_ih1 = (const float*)d_in[5];
    const float* w_hh1 = (const float*)d_in[6];
    const float* b_ih1 = (const float*)d_in[7];
    const float* b_hh1 = (const float*)d_in[8];
    const float* w_fc  = (const float*)d_in[9];
    const float* b_fc  = (const float*)d_in[10];

    const size_t smem_bytes = (size_t)SMEM_FLOATS * sizeof(float);
    cudaFuncSetAttribute(lstm_persistent_kernel,
                         cudaFuncAttributeMaxDynamicSharedMemorySize, (int)smem_bytes);
    lstm_persistent_kernel<<<NB, NTHREADS, smem_bytes>>>(
        x, w_ih0, w_hh0, b_ih0, b_hh0, w_ih1, w_hh1, b_ih1, b_hh1, w_fc, b_fc,
        (float*)d_out);
}

// round 4
// speedup vs baseline: 1.2389x; 1.2389x over previous
#include <cuda_runtime.h>
#include <cstddef>

// LSTM_824633721296: 2-layer LSTM (B=1024, T=512, I=8, H=64) + FC (O=10)
// 128 blocks x 128 threads (4 warps). Thread = 2 gate rows (tid, tid+128) x ALL
// 8 batches -> weights read ONCE per block-step at full crossbar bandwidth
// (32 distinct granules per LDS.128 = 4 wf = 128B/wf); A operands are
// full-warp-uniform broadcasts (1 wf). k-packed f32x2 FFMA2 accumulators.

#define BT        8
#define NB        128
#define NTHREADS  128
#define HID       64
#define NG        256
#define TSTEPS    512
#define IDIM      8
#define ODIM      10

#define W0_STRIDE 76      // 19 f4 (odd) -> 32 consecutive rows conflict-free
#define W1_STRIDE 132     // 33 f4 (odd)
#define HSTR      72      // 18 f4 per h row
#define XSTR      8
#define GSTR      272     // 272 mod 32 = 16 -> elem 2-batch gate loads conflict-free

// smem layout (floats)
#define OFF_W0    0
#define OFF_W1    (OFF_W0 + 256*W0_STRIDE)        // 19456
#define OFF_G     (OFF_W1 + 256*W1_STRIDE)        // 53248
#define OFF_H0    (OFF_G  + BT*GSTR)              // 55424
#define OFF_H1    (OFF_H0 + 2*BT*HSTR)            // 56576
#define OFF_XS    (OFF_H1 + 2*BT*HSTR)            // 57728
#define SMEM_FLOATS (OFF_XS + 2*BT*XSTR)          // 57856 floats = 231424 B

__device__ __forceinline__ float sigm_(float x) {
    return __fdividef(1.0f, 1.0f + __expf(-x));
}
__device__ __forceinline__ float tanh_(float x) {
    return 1.0f - __fdividef(2.0f, __expf(2.0f * x) + 1.0f);
}

__device__ __forceinline__ void ffma2(unsigned long long& acc,
                                      unsigned long long a,
                                      unsigned long long w) {
    asm("fma.rn.f32x2 %0, %1, %2, %0;" : "+l"(acc) : "l"(a), "l"(w));
}
__device__ __forceinline__ float hsum2(unsigned long long v) {
    float lo, hi;
    asm("mov.b64 {%0, %1}, %2;" : "=f"(lo), "=f"(hi) : "l"(v));
    return lo + hi;
}
__device__ __forceinline__ unsigned long long packbias(float b) {
    return (unsigned long long)__float_as_uint(b);
}

extern __shared__ float smem[];

__global__ void __launch_bounds__(NTHREADS, 1)
lstm_persistent_kernel(const float* __restrict__ x,
                       const float* __restrict__ w_ih0, const float* __restrict__ w_hh0,
                       const float* __restrict__ b_ih0, const float* __restrict__ b_hh0,
                       const float* __restrict__ w_ih1, const float* __restrict__ w_hh1,
                       const float* __restrict__ b_ih1, const float* __restrict__ b_hh1,
                       const float* __restrict__ w_fc,  const float* __restrict__ b_fc,
                       float* __restrict__ out)
{
    float* W0    = smem + OFF_W0;   // [256][76]  cols 0..7 = w_ih0, 8..71 = w_hh0
    float* W1    = smem + OFF_W1;   // [256][132] cols 0..63 = w_ih1, 64..127 = w_hh1
    float* gates = smem + OFF_G;    // [8][272]
    float* h0s   = smem + OFF_H0;   // [2][8][72]
    float* h1s   = smem + OFF_H1;   // [2][8][72]
    float* xs    = smem + OFF_XS;   // [2][8][8]

    const int tid = threadIdx.x;
    const int b0  = blockIdx.x * BT;

    // ---- stage weights into SMEM ----
    for (int i = tid; i < 256 * 8;  i += NTHREADS) W0[(i >> 3) * W0_STRIDE + (i & 7)]       = w_ih0[i];
    for (int i = tid; i < 256 * 64; i += NTHREADS) W0[(i >> 6) * W0_STRIDE + 8 + (i & 63)]  = w_hh0[i];
    for (int i = tid; i < 256 * 64; i += NTHREADS) W1[(i >> 6) * W1_STRIDE + (i & 63)]      = w_ih1[i];
    for (int i = tid; i < 256 * 64; i += NTHREADS) W1[(i >> 6) * W1_STRIDE + 64 + (i & 63)] = w_hh1[i];
    for (int i = tid; i < 2 * BT * HSTR; i += NTHREADS) { h0s[i] = 0.0f; h1s[i] = 0.0f; }

    // x(t=0) -> xs buffer 0
    if (tid < 16) {
        int b = tid >> 1, q = tid & 1;
        float4 v = *(const float4*)(x + (size_t)(b0 + b) * TSTEPS * IDIM + q * 4);
        *(float4*)(xs + b * XSTR + q * 4) = v;
    }

    // ---- GEMM mapping: thread = rows r0 = tid, r1 = tid+128; all 8 batches ----
    const int r0 = tid;
    const int r1 = tid + 128;

    const float bias00 = b_ih0[r0] + b_hh0[r0];
    const float bias01 = b_ih0[r1] + b_hh0[r1];
    const float bias10 = b_ih1[r0] + b_hh1[r0];
    const float bias11 = b_ih1[r1] + b_hh1[r1];

    // ---- elementwise mapping: b = tid>>4, eh = (tid&15)+16j, j=0..3 ----
    const int eb  = tid >> 4;       // 0..7
    const int ehb = tid & 15;
    float c0[4] = {0.f, 0.f, 0.f, 0.f};
    float c1[4] = {0.f, 0.f, 0.f, 0.f};

    __syncthreads();

    const ulonglong2* w0a = (const ulonglong2*)(W0 + r0 * W0_STRIDE);
    const ulonglong2* w0b = (const ulonglong2*)(W0 + r1 * W0_STRIDE);
    const ulonglong2* w1a = (const ulonglong2*)(W1 + r0 * W1_STRIDE);
    const ulonglong2* w1b = (const ulonglong2*)(W1 + r1 * W1_STRIDE);

    for (int t = 0; t < TSTEPS; t++) {
        const int p  = t & 1;
        const int pn = p ^ 1;

        // prefetch x(t+1)
        float4 xpre = make_float4(0.f, 0.f, 0.f, 0.f);
        const bool doPre = (tid < 16) && (t + 1 < TSTEPS);
        if (doPre) {
            int b = tid >> 1, q = tid & 1;
            xpre = *(const float4*)(x + (size_t)(b0 + b) * TSTEPS * IDIM + (size_t)(t + 1) * IDIM + q * 4);
        }

        unsigned long long accA[8], accB[8];

        // ========== GEMM 0: gates = [x_t | h0] @ W0^T + bias ==========
        #pragma unroll
        for (int b = 0; b < 8; b++) { accA[b] = packbias(bias00); accB[b] = packbias(bias01); }
        {
            const ulonglong2* xq = (const ulonglong2*)(xs + p * (BT * XSTR));
            const ulonglong2* hq = (const ulonglong2*)(h0s + p * (BT * HSTR));
            #pragma unroll
            for (int q = 0; q < 2; q++) {            // x part (K=8)
                ulonglong2 wA = w0a[q];
                ulonglong2 wB = w0b[q];
                #pragma unroll
                for (int b = 0; b < 8; b++) {
                    ulonglong2 av = xq[b * (XSTR/4) + q];   // warp-uniform
                    ffma2(accA[b], av.x, wA.x); ffma2(accA[b], av.y, wA.y);
                    ffma2(accB[b], av.x, wB.x); ffma2(accB[b], av.y, wB.y);
                }
            }
            #pragma unroll
            for (int q = 0; q < 16; q++) {           // h part (K=64)
                ulonglong2 wA = w0a[2 + q];
                ulonglong2 wB = w0b[2 + q];
                #pragma unroll
                for (int b = 0; b < 8; b++) {
                    ulonglong2 av = hq[b * (HSTR/4) + q];   // warp-uniform
                    ffma2(accA[b], av.x, wA.x); ffma2(accA[b], av.y, wA.y);
                    ffma2(accB[b], av.x, wB.x); ffma2(accB[b], av.y, wB.y);
                }
            }
        }
        #pragma unroll
        for (int b = 0; b < 8; b++) {
            gates[b * GSTR + r0] = hsum2(accA[b]);
            gates[b * GSTR + r1] = hsum2(accB[b]);
        }
        __syncthreads();

        // ========== ELEM 0 ==========
        {
            const float* g  = gates + eb * GSTR + ehb;
            float* hdst = h0s + pn * (BT * HSTR) + eb * HSTR + ehb;
            #pragma unroll
            for (int j = 0; j < 4; j++) {
                int e = 16 * j;
                float iv = sigm_(g[e]);
                float fv = sigm_(g[64 + e]);
                float gv = tanh_(g[128 + e]);
                float ov = sigm_(g[192 + e]);
                c0[j] = fv * c0[j] + iv * gv;
                hdst[e] = ov * tanh_(c0[j]);
            }
        }
        __syncthreads();

        // ========== GEMM 1: gates = [h0_new | h1] @ W1^T + bias ==========
        #pragma unroll
        for (int b = 0; b < 8; b++) { accA[b] = packbias(bias10); accB[b] = packbias(bias11); }
        {
            const ulonglong2* h0q = (const ulonglong2*)(h0s + pn * (BT * HSTR));
            const ulonglong2* h1q = (const ulonglong2*)(h1s + p  * (BT * HSTR));
            #pragma unroll
            for (int q = 0; q < 16; q++) {           // h0_new part
                ulonglong2 wA = w1a[q];
                ulonglong2 wB = w1b[q];
                #pragma unroll
                for (int b = 0; b < 8; b++) {
                    ulonglong2 av = h0q[b * (HSTR/4) + q];
                    ffma2(accA[b], av.x, wA.x); ffma2(accA[b], av.y, wA.y);
                    ffma2(accB[b], av.x, wB.x); ffma2(accB[b], av.y, wB.y);
                }
            }
            #pragma unroll
            for (int q = 0; q < 16; q++) {           // h1 part
                ulonglong2 wA = w1a[16 + q];
                ulonglong2 wB = w1b[16 + q];
                #pragma unroll
                for (int b = 0; b < 8; b++) {
                    ulonglong2 av = h1q[b * (HSTR/4) + q];
                    ffma2(accA[b], av.x, wA.x); ffma2(accA[b], av.y, wA.y);
                    ffma2(accB[b], av.x, wB.x); ffma2(accB[b], av.y, wB.y);
                }
            }
        }
        #pragma unroll
        for (int b = 0; b < 8; b++) {
            gates[b * GSTR + r0] = hsum2(accA[b]);
            gates[b * GSTR + r1] = hsum2(accB[b]);
        }
        if (doPre) {
            int b = tid >> 1, q = tid & 1;
            *(float4*)(xs + pn * (BT * XSTR) + b * XSTR + q * 4) = xpre;
        }
        __syncthreads();

        // ========== ELEM 1 ==========
        {
            const float* g  = gates + eb * GSTR + ehb;
            float* hdst = h1s + pn * (BT * HSTR) + eb * HSTR + ehb;
            #pragma unroll
            for (int j = 0; j < 4; j++) {
                int e = 16 * j;
                float iv = sigm_(g[e]);
                float fv = sigm_(g[64 + e]);
                float gv = tanh_(g[128 + e]);
                float ov = sigm_(g[192 + e]);
                c1[j] = fv * c1[j] + iv * gv;
                hdst[e] = ov * tanh_(c1[j]);
            }
        }
        __syncthreads();
    }

    // ========== FC: out = h1_final @ w_fc^T + b_fc ==========
    // after t=511: p=1 -> final h1 in buffer 0
    if (tid < BT * ODIM) {
        int b = tid / ODIM, o = tid % ODIM;
        const float* hrow = h1s + b * HSTR;
        const float* wrow = w_fc + o * HID;
        float s = b_fc[o];
        #pragma unroll 16
        for (int k = 0; k < HID; k++) s = fmaf(hrow[k], wrow[k], s);
        out[(size_t)(b0 + b) * ODIM + o] = s;
    }
}

extern "C" void kernel_launch(void* const* d_in, const int* in_sizes, int n_in,
                              void* d_out, int out_size)
{
    (void)in_sizes; (void)n_in; (void)out_size;
    const float* x     = (const float*)d_in[0];
    const float* w_ih0 = (const float*)d_in[1];
    const float* w_hh0 = (const float*)d_in[2];
    const float* b_ih0 = (const float*)d_in[3];
    const float* b_hh0 = (const float*)d_in[4];
    const float* w_ih1 = (const float*)d_in[5];
    const float* w_hh1 = (const float*)d_in[6];
    const float* b_ih1 = (const float*)d_in[7];
    const float* b_hh1 = (const float*)d_in[8];
    const float* w_fc  = (const float*)d_in[9];
    const float* b_fc  = (const float*)d_in[10];

    const size_t smem_bytes = (size_t)SMEM_FLOATS * sizeof(float);
    cudaFuncSetAttribute(lstm_persistent_kernel,
                         cudaFuncAttributeMaxDynamicSharedMemorySize, (int)smem_bytes);
    lstm_persistent_kernel<<<NB, NTHREADS, smem_bytes>>>(
        x, w_ih0, w_hh0, b_ih0, b_hh0, w_ih1, w_hh1, b_ih1, b_hh1, w_fc, b_fc,
        (float*)d_out);
}